// round 2
// baseline (speedup 1.0000x reference)
#include <cuda_runtime.h>

#define D_IN   150528
#define FEAT   256
#define NHID   64
#define NT     4
#define NB     8

#define KSPLIT 21
#define KCHUNK 7168      /* D_IN / KSPLIT */
#define KT     1024
#define KT4    256       /* KT/4 */
#define NTILES 7         /* KCHUNK / KT */
#define RF     8
#define FGROUPS 32       /* FEAT / RF */
#define NW     5         /* W1 + 4 task dW1 */

// Scratch (device globals; no runtime allocation)
__device__ float d_gpart[KSPLIT][NW][FEAT][NB];
__device__ float d_u[NB][FEAT];
__device__ float d_hrelu[NB][FEAT];
__device__ float d_base[NB][FEAT];
__device__ float d_coefs[NB][NT];

// ---------------------------------------------------------------------------
// Kernel 1: streaming dot products. g[j][f][b] = x[b] . Wj[f]  (no biases yet)
// Each block: 8 f-values x 5 tensors over one k-chunk; x tile staged in SMEM.
// ---------------------------------------------------------------------------
__global__ __launch_bounds__(256, 2)
void big_kernel(const float* __restrict__ x,
                const float* __restrict__ W1,
                const float* __restrict__ dW1)
{
    __shared__ float4 xs[NB][KT4];   // 32 KB

    const int tid  = threadIdx.x;
    const int lane = tid & 31;
    const int warp = tid >> 5;
    const int ks   = blockIdx.x;
    const int f    = blockIdx.y * RF + warp;
    const long k0  = (long)ks * KCHUNK;

    const float4* __restrict__ wrow[NW];
    wrow[0] = (const float4*)(W1 + (long)f * D_IN + k0);
    #pragma unroll
    for (int t = 0; t < NT; t++)
        wrow[t + 1] = (const float4*)(dW1 + ((long)(t * FEAT + f)) * D_IN + k0);

    float acc[NW][NB];
    #pragma unroll
    for (int j = 0; j < NW; j++)
        #pragma unroll
        for (int b = 0; b < NB; b++) acc[j][b] = 0.0f;

    for (int tile = 0; tile < NTILES; tile++) {
        __syncthreads();
        {
            const long kbase = k0 + (long)tile * KT;
            #pragma unroll
            for (int i = tid; i < NB * KT4; i += 256) {
                int b  = i >> 8;          // KT4 == 256
                int kq = i & (KT4 - 1);
                xs[b][kq] = *(const float4*)(x + (long)b * D_IN + kbase + 4 * kq);
            }
        }
        __syncthreads();

        #pragma unroll 2
        for (int i = 0; i < KT4 / 32; i++) {   // 8 iterations
            const int kq = lane + 32 * i;
            float4 xv[NB];
            #pragma unroll
            for (int b = 0; b < NB; b++) xv[b] = xs[b][kq];
            const int widx = tile * KT4 + kq;
            #pragma unroll
            for (int j = 0; j < NW; j++) {
                const float4 wv = __ldcs(wrow[j] + widx);
                #pragma unroll
                for (int b = 0; b < NB; b++) {
                    acc[j][b] = fmaf(wv.x, xv[b].x, acc[j][b]);
                    acc[j][b] = fmaf(wv.y, xv[b].y, acc[j][b]);
                    acc[j][b] = fmaf(wv.z, xv[b].z, acc[j][b]);
                    acc[j][b] = fmaf(wv.w, xv[b].w, acc[j][b]);
                }
            }
        }
    }

    // warp butterfly reduction, then lane b stores batch b
    #pragma unroll
    for (int j = 0; j < NW; j++)
        #pragma unroll
        for (int b = 0; b < NB; b++) {
            float v = acc[j][b];
            #pragma unroll
            for (int off = 16; off; off >>= 1)
                v += __shfl_xor_sync(0xffffffffu, v, off);
            if (lane == b) d_gpart[ks][j][f][b] = v;
        }
}

// ---------------------------------------------------------------------------
// Kernel 2 (1 block): reduce partials, biases, relu, base, MetaNet coefs, u
// ---------------------------------------------------------------------------
__global__ __launch_bounds__(256)
void mid_kernel(const float* __restrict__ b1,  const float* __restrict__ W2,
                const float* __restrict__ b2,  const float* __restrict__ mW1,
                const float* __restrict__ mb1, const float* __restrict__ mW2,
                const float* __restrict__ mb2, const float* __restrict__ db1)
{
    __shared__ float hrelu_s[FEAT][NB];   // 8 KB
    __shared__ float base_s[NB][FEAT];    // 8 KB
    __shared__ float hid_s[NB][NHID];     // 2 KB
    __shared__ float coef_s[NB][NT];

    const int tid = threadIdx.x;          // == f for phases 1 & 4

    float z[NW][NB];
    #pragma unroll
    for (int j = 0; j < NW; j++)
        #pragma unroll
        for (int b = 0; b < NB; b++) z[j][b] = 0.0f;

    for (int ks = 0; ks < KSPLIT; ks++) {
        #pragma unroll
        for (int j = 0; j < NW; j++) {
            const float4* gp = (const float4*)&d_gpart[ks][j][tid][0];
            float4 a = gp[0], c = gp[1];
            z[j][0] += a.x; z[j][1] += a.y; z[j][2] += a.z; z[j][3] += a.w;
            z[j][4] += c.x; z[j][5] += c.y; z[j][6] += c.z; z[j][7] += c.w;
        }
    }
    {
        const float bb = b1[tid];
        #pragma unroll
        for (int b = 0; b < NB; b++) {
            z[0][b] += bb;
            hrelu_s[tid][b] = fmaxf(z[0][b], 0.0f);
        }
        #pragma unroll
        for (int t = 0; t < NT; t++) {
            const float dbb = db1[t * FEAT + tid];
            #pragma unroll
            for (int b = 0; b < NB; b++) z[t + 1][b] += dbb;
        }
    }
    __syncthreads();

    // base[b][f2], f2 = tid
    {
        float bacc[NB];
        #pragma unroll
        for (int b = 0; b < NB; b++) bacc[b] = 0.0f;
        for (int ff = 0; ff < FEAT; ff++) {
            const float w = W2[tid * FEAT + ff];
            #pragma unroll
            for (int b = 0; b < NB; b++) bacc[b] = fmaf(hrelu_s[ff][b], w, bacc[b]);
        }
        const float bb2 = b2[tid];
        #pragma unroll
        for (int b = 0; b < NB; b++) base_s[b][tid] = bacc[b] + bb2;
    }
    __syncthreads();

    // MetaNet hidden: 512 outputs over 256 threads
    #pragma unroll
    for (int r = 0; r < 2; r++) {
        const int idx = tid + 256 * r;
        const int b = idx / NHID, h = idx % NHID;
        float a = mb1[h];
        for (int ff = 0; ff < FEAT; ff++) a = fmaf(base_s[b][ff], mW1[h * FEAT + ff], a);
        hid_s[b][h] = fmaxf(a, 0.0f);
    }
    __syncthreads();

    if (tid < NB * NT) {
        const int b = tid / NT, t = tid % NT;
        float a = mb2[t];
        for (int h = 0; h < NHID; h++) a = fmaf(hid_s[b][h], mW2[t * NHID + h], a);
        coef_s[b][t] = a;
        d_coefs[b][t] = a;
    }
    __syncthreads();

    // u[b][f] = sum_t coef * masked tangent hidden; export tensors
    #pragma unroll
    for (int b = 0; b < NB; b++) {
        float uu = 0.0f;
        if (z[0][b] > 0.0f) {
            #pragma unroll
            for (int t = 0; t < NT; t++) uu = fmaf(coef_s[b][t], z[t + 1][b], uu);
        }
        d_u[b][tid]     = uu;
        d_hrelu[b][tid] = hrelu_s[tid][b];
        d_base[b][tid]  = base_s[b][tid];
    }
}

// ---------------------------------------------------------------------------
// Kernel 3: out[b][f2] = base + u.W2[f2] + sum_t c*(hrelu.dW2[t][f2] + db2)
// one block per f2; warp w handles batch b = w; coalesced over f.
// ---------------------------------------------------------------------------
__global__ __launch_bounds__(256)
void out_kernel(const float* __restrict__ W2, const float* __restrict__ dW2,
                const float* __restrict__ db2, float* __restrict__ out)
{
    const int f2   = blockIdx.x;
    const int lane = threadIdx.x & 31;
    const int b    = threadIdx.x >> 5;

    float accW = 0.0f;
    float accD[NT] = {0.0f, 0.0f, 0.0f, 0.0f};

    #pragma unroll
    for (int i = 0; i < FEAT / 32; i++) {
        const int f = lane + 32 * i;
        const float u  = d_u[b][f];
        const float hr = d_hrelu[b][f];
        accW = fmaf(u, W2[f2 * FEAT + f], accW);
        #pragma unroll
        for (int t = 0; t < NT; t++)
            accD[t] = fmaf(hr, dW2[((t * FEAT + f2) * FEAT) + f], accD[t]);
    }

    #pragma unroll
    for (int off = 16; off; off >>= 1) {
        accW += __shfl_xor_sync(0xffffffffu, accW, off);
        #pragma unroll
        for (int t = 0; t < NT; t++)
            accD[t] += __shfl_xor_sync(0xffffffffu, accD[t], off);
    }

    if (lane == 0) {
        float o = d_base[b][f2] + accW;
        #pragma unroll
        for (int t = 0; t < NT; t++)
            o += d_coefs[b][t] * (accD[t] + db2[t * FEAT + f2]);
        out[b * FEAT + f2] = o;
    }
}

// ---------------------------------------------------------------------------
extern "C" void kernel_launch(void* const* d_in, const int* in_sizes, int n_in,
                              void* d_out, int out_size)
{
    (void)in_sizes; (void)n_in; (void)out_size;
    const float* x   = (const float*)d_in[0];
    const float* W1  = (const float*)d_in[1];
    const float* b1  = (const float*)d_in[2];
    const float* W2  = (const float*)d_in[3];
    const float* b2  = (const float*)d_in[4];
    const float* mW1 = (const float*)d_in[5];
    const float* mb1 = (const float*)d_in[6];
    const float* mW2 = (const float*)d_in[7];
    const float* mb2 = (const float*)d_in[8];
    const float* dW1 = (const float*)d_in[9];
    const float* db1 = (const float*)d_in[10];
    const float* dW2 = (const float*)d_in[11];
    const float* db2 = (const float*)d_in[12];
    float* out = (float*)d_out;

    big_kernel<<<dim3(KSPLIT, FGROUPS), 256>>>(x, W1, dW1);
    mid_kernel<<<1, 256>>>(b1, W2, b2, mW1, mb1, mW2, mb2, db1);
    out_kernel<<<FEAT, 256>>>(W2, dW2, db2, out);
}

// round 8
// speedup vs baseline: 1.0586x; 1.0586x over previous
#include <cuda_runtime.h>

#define D_IN   150528
#define FEAT   256
#define NHID   64
#define NT     4
#define NB     8

#define KSPLIT 49
#define KCHUNK 3072      /* D_IN / KSPLIT */
#define KT     512
#define KT4    128       /* KT/4 */
#define NTILES 6         /* KCHUNK / KT */
#define RF     8
#define FGROUPS 32       /* FEAT / RF */
#define NW     5         /* W1 + 4 task dW1 */

// Scratch (device globals; no runtime allocation)
__device__ float d_gpart[KSPLIT][NW][FEAT][NB];   // ~2 MB
__device__ float d_hrelu[NB][FEAT];
__device__ float d_mt[NT][NB][FEAT];              // masked tangent hidden
__device__ float d_base[NB][FEAT];
__device__ float d_wv[NT][NB][FEAT];              // (mt@W2^T + hrelu@dW2^T + db2) per task

__device__ __forceinline__ void cpa16(void* smem_dst, const void* gsrc) {
    unsigned saddr = (unsigned)__cvta_generic_to_shared(smem_dst);
    asm volatile("cp.async.cg.shared.global [%0], [%1], 16;\n" :: "r"(saddr), "l"(gsrc));
}
__device__ __forceinline__ void cpa_commit() {
    asm volatile("cp.async.commit_group;\n" ::: "memory");
}
template<int N> __device__ __forceinline__ void cpa_wait() {
    asm volatile("cp.async.wait_group %0;\n" :: "n"(N) : "memory");
}

// ---------------------------------------------------------------------------
// Kernel 1: streaming dot products. g[j][f][b] = x[b] . Wj[f]  (no biases)
// Double-buffered x tile via cp.async; 8 f x 5 tensors per block.
// ---------------------------------------------------------------------------
__global__ __launch_bounds__(256, 2)
void big_kernel(const float* __restrict__ x,
                const float* __restrict__ W1,
                const float* __restrict__ dW1)
{
    __shared__ float4 xs[2][NB][KT4];   // 2 x 16 KB

    const int tid  = threadIdx.x;
    const int lane = tid & 31;
    const int warp = tid >> 5;
    const int ks   = blockIdx.x;
    const int f    = blockIdx.y * RF + warp;
    const long k0  = (long)ks * KCHUNK;

    const float4* __restrict__ wrow[NW];
    wrow[0] = (const float4*)(W1 + (long)f * D_IN + k0);
    #pragma unroll
    for (int t = 0; t < NT; t++)
        wrow[t + 1] = (const float4*)(dW1 + ((long)(t * FEAT + f)) * D_IN + k0);

    float acc[NW][NB];
    #pragma unroll
    for (int j = 0; j < NW; j++)
        #pragma unroll
        for (int b = 0; b < NB; b++) acc[j][b] = 0.0f;

    // prologue: prefetch tile 0 into buf 0
    {
        const long kbase = k0;
        #pragma unroll
        for (int i = tid; i < NB * KT4; i += 256) {
            int b  = i >> 7;            // KT4 == 128
            int kq = i & (KT4 - 1);
            cpa16(&xs[0][b][kq], x + (long)b * D_IN + kbase + 4 * kq);
        }
        cpa_commit();
    }

    for (int tile = 0; tile < NTILES; tile++) {
        const int buf = tile & 1;
        if (tile + 1 < NTILES) {
            const long kbase = k0 + (long)(tile + 1) * KT;
            #pragma unroll
            for (int i = tid; i < NB * KT4; i += 256) {
                int b  = i >> 7;
                int kq = i & (KT4 - 1);
                cpa16(&xs[buf ^ 1][b][kq], x + (long)b * D_IN + kbase + 4 * kq);
            }
            cpa_commit();
            cpa_wait<1>();
        } else {
            cpa_wait<0>();
        }
        __syncthreads();

        #pragma unroll 2
        for (int i = 0; i < KT4 / 32; i++) {   // 4 iterations
            const int kq = lane + 32 * i;
            float4 xv[NB];
            #pragma unroll
            for (int b = 0; b < NB; b++) xv[b] = xs[buf][b][kq];
            const int widx = tile * KT4 + kq;
            #pragma unroll
            for (int j = 0; j < NW; j++) {
                const float4 wv = __ldcs(wrow[j] + widx);
                #pragma unroll
                for (int b = 0; b < NB; b++) {
                    acc[j][b] = fmaf(wv.x, xv[b].x, acc[j][b]);
                    acc[j][b] = fmaf(wv.y, xv[b].y, acc[j][b]);
                    acc[j][b] = fmaf(wv.z, xv[b].z, acc[j][b]);
                    acc[j][b] = fmaf(wv.w, xv[b].w, acc[j][b]);
                }
            }
        }
        __syncthreads();   // protect buf we just read before it is refilled
    }

    // warp butterfly reduction, then lane b stores batch b
    #pragma unroll
    for (int j = 0; j < NW; j++)
        #pragma unroll
        for (int b = 0; b < NB; b++) {
            float v = acc[j][b];
            #pragma unroll
            for (int off = 16; off; off >>= 1)
                v += __shfl_xor_sync(0xffffffffu, v, off);
            if (lane == b) d_gpart[blockIdx.x][j][f][b] = v;
        }
}

// ---------------------------------------------------------------------------
// Kernel 2 (1 block): reduce partials -> z; emit hrelu + masked tangents
// ---------------------------------------------------------------------------
__global__ __launch_bounds__(256)
void red_kernel(const float* __restrict__ b1, const float* __restrict__ db1)
{
    const int tid = threadIdx.x;   // == f

    float z[NW][NB];
    #pragma unroll
    for (int j = 0; j < NW; j++)
        #pragma unroll
        for (int b = 0; b < NB; b++) z[j][b] = 0.0f;

    #pragma unroll 2
    for (int ks = 0; ks < KSPLIT; ks++) {
        #pragma unroll
        for (int j = 0; j < NW; j++) {
            const float4* gp = (const float4*)&d_gpart[ks][j][tid][0];
            float4 a = gp[0], c = gp[1];
            z[j][0] += a.x; z[j][1] += a.y; z[j][2] += a.z; z[j][3] += a.w;
            z[j][4] += c.x; z[j][5] += c.y; z[j][6] += c.z; z[j][7] += c.w;
        }
    }

    const float bb = b1[tid];
    #pragma unroll
    for (int b = 0; b < NB; b++) {
        z[0][b] += bb;
        d_hrelu[b][tid] = fmaxf(z[0][b], 0.0f);
    }
    #pragma unroll
    for (int t = 0; t < NT; t++) {
        const float dbb = db1[t * FEAT + tid];
        #pragma unroll
        for (int b = 0; b < NB; b++)
            d_mt[t][b][tid] = (z[0][b] > 0.0f) ? (z[t + 1][b] + dbb) : 0.0f;
    }
}

// ---------------------------------------------------------------------------
// Kernel 3 (256 blocks): all coef-independent matrix terms.
//   base[b][f2] = hrelu[b] . W2[f2] + b2[f2]
//   wv[t][b][f2] = mt[t][b] . W2[f2] + hrelu[b] . dW2[t][f2] + db2[t][f2]
// block = f2; warp = batch; lane over f (coalesced).
// ---------------------------------------------------------------------------
__global__ __launch_bounds__(256)
void mat_kernel(const float* __restrict__ W2, const float* __restrict__ b2,
                const float* __restrict__ dW2, const float* __restrict__ db2)
{
    const int f2   = blockIdx.x;
    const int lane = threadIdx.x & 31;
    const int b    = threadIdx.x >> 5;

    float accB = 0.0f;
    float accW[NT] = {0.f, 0.f, 0.f, 0.f};
    float accV[NT] = {0.f, 0.f, 0.f, 0.f};

    #pragma unroll
    for (int i = 0; i < FEAT / 32; i++) {
        const int f = lane + 32 * i;
        const float hr = d_hrelu[b][f];
        const float w2 = W2[f2 * FEAT + f];
        accB = fmaf(hr, w2, accB);
        #pragma unroll
        for (int t = 0; t < NT; t++) {
            const float mt = d_mt[t][b][f];
            accW[t] = fmaf(mt, w2, accW[t]);
            const float dv = dW2[((t * FEAT + f2) * FEAT) + f];
            accV[t] = fmaf(hr, dv, accV[t]);
        }
    }

    #pragma unroll
    for (int off = 16; off; off >>= 1) {
        accB += __shfl_xor_sync(0xffffffffu, accB, off);
        #pragma unroll
        for (int t = 0; t < NT; t++) {
            accW[t] += __shfl_xor_sync(0xffffffffu, accW[t], off);
            accV[t] += __shfl_xor_sync(0xffffffffu, accV[t], off);
        }
    }

    if (lane == 0) {
        d_base[b][f2] = accB + b2[f2];
        #pragma unroll
        for (int t = 0; t < NT; t++)
            d_wv[t][b][f2] = accW[t] + accV[t] + db2[t * FEAT + f2];
    }
}

// ---------------------------------------------------------------------------
// Kernel 4 (1 block): MetaNet coefs + final combine
// ---------------------------------------------------------------------------
__global__ __launch_bounds__(256)
void fin_kernel(const float* __restrict__ mW1, const float* __restrict__ mb1,
                const float* __restrict__ mW2, const float* __restrict__ mb2,
                float* __restrict__ out)
{
    __shared__ float base_s[NB][FEAT];   // 8 KB
    __shared__ float hid_s[NB][NHID];    // 2 KB
    __shared__ float coef_s[NB][NT];

    const int tid = threadIdx.x;

    #pragma unroll
    for (int b = 0; b < NB; b++) base_s[b][tid] = d_base[b][tid];
    __syncthreads();

    #pragma unroll
    for (int r = 0; r < 2; r++) {
        const int idx = tid + 256 * r;
        const int b = idx / NHID, h = idx % NHID;
        float a = mb1[h];
        #pragma unroll 4
        for (int ff = 0; ff < FEAT; ff++)
            a = fmaf(base_s[b][ff], mW1[h * FEAT + ff], a);
        hid_s[b][h] = fmaxf(a, 0.0f);
    }
    __syncthreads();

    if (tid < NB * NT) {
        const int b = tid / NT, t = tid % NT;
        float a = mb2[t];
        #pragma unroll 4
        for (int h = 0; h < NHID; h++)
            a = fmaf(hid_s[b][h], mW2[t * NHID + h], a);
        coef_s[b][t] = a;
    }
    __syncthreads();

    #pragma unroll
    for (int b = 0; b < NB; b++) {
        float o = base_s[b][tid];
        #pragma unroll
        for (int t = 0; t < NT; t++)
            o = fmaf(coef_s[b][t], d_wv[t][b][tid], o);
        out[b * FEAT + tid] = o;
    }
}

// ---------------------------------------------------------------------------
extern "C" void kernel_launch(void* const* d_in, const int* in_sizes, int n_in,
                              void* d_out, int out_size)
{
    (void)in_sizes; (void)n_in; (void)out_size;
    const float* x   = (const float*)d_in[0];
    const float* W1  = (const float*)d_in[1];
    const float* b1  = (const float*)d_in[2];
    const float* W2  = (const float*)d_in[3];
    const float* b2  = (const float*)d_in[4];
    const float* mW1 = (const float*)d_in[5];
    const float* mb1 = (const float*)d_in[6];
    const float* mW2 = (const float*)d_in[7];
    const float* mb2 = (const float*)d_in[8];
    const float* dW1 = (const float*)d_in[9];
    const float* db1 = (const float*)d_in[10];
    const float* dW2 = (const float*)d_in[11];
    const float* db2 = (const float*)d_in[12];
    float* out = (float*)d_out;

    big_kernel<<<dim3(KSPLIT, FGROUPS), 256>>>(x, W1, dW1);
    red_kernel<<<1, 256>>>(b1, db1);
    mat_kernel<<<FEAT, 256>>>(W2, b2, dW2, db2);
    fin_kernel<<<1, 256>>>(mW1, mb1, mW2, mb2, out);
}

// round 10
// speedup vs baseline: 1.5173x; 1.4333x over previous
#include <cuda_runtime.h>

#define D_IN   150528
#define FEAT   256
#define NHID   64
#define NT     4
#define NB     8

#define KSPLIT 49
#define KCHUNK 3072      /* D_IN / KSPLIT */
#define KT     512
#define KT4    128       /* KT/4 */
#define NTILES 6         /* KCHUNK / KT */
#define RF     8
#define FGROUPS 32       /* FEAT / RF */
#define NW     5         /* W1 + 4 task dW1 */

// Scratch (device globals; no runtime allocation)
__device__ float d_gpart[KSPLIT][NW][FEAT][NB];   // ~2 MB
__device__ float d_hrelu[NB][FEAT];
__device__ float d_mt[NT][NB][FEAT];              // masked tangent hidden
__device__ float d_base[NB][FEAT];
__device__ float d_wv[NT][NB][FEAT];              // (mt@W2^T + hrelu@dW2^T + db2) per task

__device__ __forceinline__ void cpa16(void* smem_dst, const void* gsrc) {
    unsigned saddr = (unsigned)__cvta_generic_to_shared(smem_dst);
    asm volatile("cp.async.cg.shared.global [%0], [%1], 16;\n" :: "r"(saddr), "l"(gsrc));
}
__device__ __forceinline__ void cpa_commit() {
    asm volatile("cp.async.commit_group;\n" ::: "memory");
}
template<int N> __device__ __forceinline__ void cpa_wait() {
    asm volatile("cp.async.wait_group %0;\n" :: "n"(N) : "memory");
}

// ---------------------------------------------------------------------------
// Kernel 1: streaming dot products. g[j][f][b] = x[b] . Wj[f]  (no biases)
// Double-buffered x tile via cp.async; 8 f x 5 tensors per block. (FROZEN)
// ---------------------------------------------------------------------------
__global__ __launch_bounds__(256, 2)
void big_kernel(const float* __restrict__ x,
                const float* __restrict__ W1,
                const float* __restrict__ dW1)
{
    __shared__ float4 xs[2][NB][KT4];   // 2 x 16 KB

    const int tid  = threadIdx.x;
    const int lane = tid & 31;
    const int warp = tid >> 5;
    const int ks   = blockIdx.x;
    const int f    = blockIdx.y * RF + warp;
    const long k0  = (long)ks * KCHUNK;

    const float4* __restrict__ wrow[NW];
    wrow[0] = (const float4*)(W1 + (long)f * D_IN + k0);
    #pragma unroll
    for (int t = 0; t < NT; t++)
        wrow[t + 1] = (const float4*)(dW1 + ((long)(t * FEAT + f)) * D_IN + k0);

    float acc[NW][NB];
    #pragma unroll
    for (int j = 0; j < NW; j++)
        #pragma unroll
        for (int b = 0; b < NB; b++) acc[j][b] = 0.0f;

    // prologue: prefetch tile 0 into buf 0
    {
        const long kbase = k0;
        #pragma unroll
        for (int i = tid; i < NB * KT4; i += 256) {
            int b  = i >> 7;            // KT4 == 128
            int kq = i & (KT4 - 1);
            cpa16(&xs[0][b][kq], x + (long)b * D_IN + kbase + 4 * kq);
        }
        cpa_commit();
    }

    for (int tile = 0; tile < NTILES; tile++) {
        const int buf = tile & 1;
        if (tile + 1 < NTILES) {
            const long kbase = k0 + (long)(tile + 1) * KT;
            #pragma unroll
            for (int i = tid; i < NB * KT4; i += 256) {
                int b  = i >> 7;
                int kq = i & (KT4 - 1);
                cpa16(&xs[buf ^ 1][b][kq], x + (long)b * D_IN + kbase + 4 * kq);
            }
            cpa_commit();
            cpa_wait<1>();
        } else {
            cpa_wait<0>();
        }
        __syncthreads();

        #pragma unroll 2
        for (int i = 0; i < KT4 / 32; i++) {   // 4 iterations
            const int kq = lane + 32 * i;
            float4 xv[NB];
            #pragma unroll
            for (int b = 0; b < NB; b++) xv[b] = xs[buf][b][kq];
            const int widx = tile * KT4 + kq;
            #pragma unroll
            for (int j = 0; j < NW; j++) {
                const float4 wv = __ldcs(wrow[j] + widx);
                #pragma unroll
                for (int b = 0; b < NB; b++) {
                    acc[j][b] = fmaf(wv.x, xv[b].x, acc[j][b]);
                    acc[j][b] = fmaf(wv.y, xv[b].y, acc[j][b]);
                    acc[j][b] = fmaf(wv.z, xv[b].z, acc[j][b]);
                    acc[j][b] = fmaf(wv.w, xv[b].w, acc[j][b]);
                }
            }
        }
        __syncthreads();   // protect buf we just read before it is refilled
    }

    // warp butterfly reduction, then lane b stores batch b
    #pragma unroll
    for (int j = 0; j < NW; j++)
        #pragma unroll
        for (int b = 0; b < NB; b++) {
            float v = acc[j][b];
            #pragma unroll
            for (int off = 16; off; off >>= 1)
                v += __shfl_xor_sync(0xffffffffu, v, off);
            if (lane == b) d_gpart[blockIdx.x][j][f][b] = v;
        }
}

// ---------------------------------------------------------------------------
// Kernel 2 (32 blocks): reduce partials -> z; emit hrelu + masked tangents.
// warp w of block handles f = blockIdx*8 + w; lanes parallel over ksplit.
// ---------------------------------------------------------------------------
__global__ __launch_bounds__(256)
void red_kernel(const float* __restrict__ b1, const float* __restrict__ db1)
{
    const int lane = threadIdx.x & 31;
    const int wid  = threadIdx.x >> 5;
    const int f    = blockIdx.x * 8 + wid;

    float acc[NW][NB];
    #pragma unroll
    for (int j = 0; j < NW; j++)
        #pragma unroll
        for (int b = 0; b < NB; b++) acc[j][b] = 0.0f;

    // lane covers ks = lane and ks = lane + 32 (KSPLIT = 49)
    #pragma unroll
    for (int r = 0; r < 2; r++) {
        const int s = lane + 32 * r;
        if (s < KSPLIT) {
            #pragma unroll
            for (int j = 0; j < NW; j++) {
                const float4* gp = (const float4*)&d_gpart[s][j][f][0];
                float4 a = gp[0], c = gp[1];
                acc[j][0] += a.x; acc[j][1] += a.y; acc[j][2] += a.z; acc[j][3] += a.w;
                acc[j][4] += c.x; acc[j][5] += c.y; acc[j][6] += c.z; acc[j][7] += c.w;
            }
        }
    }

    // butterfly-reduce all 40 values across the warp (every lane ends with sums)
    #pragma unroll
    for (int off = 16; off; off >>= 1)
        #pragma unroll
        for (int j = 0; j < NW; j++)
            #pragma unroll
            for (int b = 0; b < NB; b++)
                acc[j][b] += __shfl_xor_sync(0xffffffffu, acc[j][b], off);

    // lane b (0..7) emits batch b for this f
    if (lane < NB) {
        const int b = lane;
        const float z0 = acc[0][b] + b1[f];
        d_hrelu[b][f] = fmaxf(z0, 0.0f);
        #pragma unroll
        for (int t = 0; t < NT; t++)
            d_mt[t][b][f] = (z0 > 0.0f) ? (acc[t + 1][b] + db1[t * FEAT + f]) : 0.0f;
    }
}

// ---------------------------------------------------------------------------
// Kernel 3 (256 blocks): all coef-independent matrix terms. (FROZEN)
//   base[b][f2] = hrelu[b] . W2[f2] + b2[f2]
//   wv[t][b][f2] = mt[t][b] . W2[f2] + hrelu[b] . dW2[t][f2] + db2[t][f2]
// ---------------------------------------------------------------------------
__global__ __launch_bounds__(256)
void mat_kernel(const float* __restrict__ W2, const float* __restrict__ b2,
                const float* __restrict__ dW2, const float* __restrict__ db2)
{
    const int f2   = blockIdx.x;
    const int lane = threadIdx.x & 31;
    const int b    = threadIdx.x >> 5;

    float accB = 0.0f;
    float accW[NT] = {0.f, 0.f, 0.f, 0.f};
    float accV[NT] = {0.f, 0.f, 0.f, 0.f};

    #pragma unroll
    for (int i = 0; i < FEAT / 32; i++) {
        const int f = lane + 32 * i;
        const float hr = d_hrelu[b][f];
        const float w2 = W2[f2 * FEAT + f];
        accB = fmaf(hr, w2, accB);
        #pragma unroll
        for (int t = 0; t < NT; t++) {
            const float mt = d_mt[t][b][f];
            accW[t] = fmaf(mt, w2, accW[t]);
            const float dv = dW2[((t * FEAT + f2) * FEAT) + f];
            accV[t] = fmaf(hr, dv, accV[t]);
        }
    }

    #pragma unroll
    for (int off = 16; off; off >>= 1) {
        accB += __shfl_xor_sync(0xffffffffu, accB, off);
        #pragma unroll
        for (int t = 0; t < NT; t++) {
            accW[t] += __shfl_xor_sync(0xffffffffu, accW[t], off);
            accV[t] += __shfl_xor_sync(0xffffffffu, accV[t], off);
        }
    }

    if (lane == 0) {
        d_base[b][f2] = accB + b2[f2];
        #pragma unroll
        for (int t = 0; t < NT; t++)
            d_wv[t][b][f2] = accW[t] + accV[t] + db2[t * FEAT + f2];
    }
}

// ---------------------------------------------------------------------------
// Kernel 4 (8 blocks, one per batch): MetaNet coefs + final combine.
// hidden: 4 threads per h (64-wide partial dots, shfl-combined) -> high MLP.
// ---------------------------------------------------------------------------
__global__ __launch_bounds__(256)
void fin_kernel(const float* __restrict__ mW1, const float* __restrict__ mb1,
                const float* __restrict__ mW2, const float* __restrict__ mb2,
                float* __restrict__ out)
{
    __shared__ float base_s[FEAT];
    __shared__ float hid_s[NHID];
    __shared__ float coef_s[NT];

    const int b   = blockIdx.x;
    const int tid = threadIdx.x;

    base_s[tid] = d_base[b][tid];
    __syncthreads();

    // hidden[h] : h = tid>>2, quadrant q = tid&3 sums 64 ff each
    {
        const int h = tid >> 2;
        const int q = tid & 3;
        const float* wrow = mW1 + h * FEAT + q * 64;
        const float* brow = base_s + q * 64;
        float a = 0.0f;
        #pragma unroll 8
        for (int i = 0; i < 64; i++)
            a = fmaf(brow[i], wrow[i], a);
        a += __shfl_xor_sync(0xffffffffu, a, 1);
        a += __shfl_xor_sync(0xffffffffu, a, 2);
        if (q == 0) hid_s[h] = fmaxf(a + mb1[h], 0.0f);
    }
    __syncthreads();

    // coefs: 2 threads per task t (halves of the 64-dot), combined via shfl
    if (tid < 2 * NT) {
        const int t = tid >> 1;
        const int half = tid & 1;
        float c = 0.0f;
        #pragma unroll 8
        for (int h = 0; h < 32; h++)
            c = fmaf(hid_s[half * 32 + h], mW2[t * NHID + half * 32 + h], c);
        c += __shfl_xor_sync(0x000000ffu, c, 1);
        if (half == 0) coef_s[t] = c + mb2[t];
    }
    __syncthreads();

    // combine: out[b][f2] = base + sum_t coef_t * wv[t][b][f2]
    {
        float o = base_s[tid];
        #pragma unroll
        for (int t = 0; t < NT; t++)
            o = fmaf(coef_s[t], d_wv[t][b][tid], o);
        out[b * FEAT + tid] = o;
    }
}

// ---------------------------------------------------------------------------
extern "C" void kernel_launch(void* const* d_in, const int* in_sizes, int n_in,
                              void* d_out, int out_size)
{
    (void)in_sizes; (void)n_in; (void)out_size;
    const float* x   = (const float*)d_in[0];
    const float* W1  = (const float*)d_in[1];
    const float* b1  = (const float*)d_in[2];
    const float* W2  = (const float*)d_in[3];
    const float* b2  = (const float*)d_in[4];
    const float* mW1 = (const float*)d_in[5];
    const float* mb1 = (const float*)d_in[6];
    const float* mW2 = (const float*)d_in[7];
    const float* mb2 = (const float*)d_in[8];
    const float* dW1 = (const float*)d_in[9];
    const float* db1 = (const float*)d_in[10];
    const float* dW2 = (const float*)d_in[11];
    const float* db2 = (const float*)d_in[12];
    float* out = (float*)d_out;

    big_kernel<<<dim3(KSPLIT, FGROUPS), 256>>>(x, W1, dW1);
    red_kernel<<<FEAT / 8, 256>>>(b1, db1);
    mat_kernel<<<FEAT, 256>>>(W2, b2, dW2, db2);
    fin_kernel<<<NB, 256>>>(mW1, mb1, mW2, mb2, out);
}

// round 16
// speedup vs baseline: 1.7734x; 1.1688x over previous
#include <cuda_runtime.h>

#define D_IN   150528
#define FEAT   256
#define NHID   64
#define NT     4
#define NB     8

#define KSPLIT 49
#define KCHUNK 3072      /* D_IN / KSPLIT */
#define KT     128       /* floats per pipeline tile */
#define KT4    32        /* KT/4 */
#define NTILES 24        /* KCHUNK / KT */
#define RF     8
#define FGROUPS 32       /* FEAT / RF */
#define NW     5         /* W1 + 4 task dW1 */
#define NROWS  40        /* NW * RF */

// Scratch (device globals; no runtime allocation)
__device__ float d_gpart[KSPLIT][NW][FEAT][NB];   // ~2 MB
__device__ float d_hrelu[NB][FEAT];
__device__ float d_mt[NT][NB][FEAT];              // masked tangent hidden
__device__ float d_base[NB][FEAT];
__device__ float d_wv[NT][NB][FEAT];              // (mt@W2^T + hrelu@dW2^T + db2) per task
__device__ float d_warm[FGROUPS];                 // sink for L2-warm loads

__device__ __forceinline__ void cpa16(void* smem_dst, const void* gsrc) {
    unsigned saddr = (unsigned)__cvta_generic_to_shared(smem_dst);
    asm volatile("cp.async.cg.shared.global [%0], [%1], 16;\n" :: "r"(saddr), "l"(gsrc));
}
__device__ __forceinline__ void cpa_commit() {
    asm volatile("cp.async.commit_group;\n" ::: "memory");
}
template<int N> __device__ __forceinline__ void cpa_wait() {
    asm volatile("cp.async.wait_group %0;\n" :: "n"(N) : "memory");
}

// ---------------------------------------------------------------------------
// Kernel 1: streaming dot products. g[j][f][b] = x[b] . Wj[f]  (no biases)
// BOTH weights and x staged through SMEM via cp.async double buffer:
// per-CTA in-flight bytes = 24 KB >> Little's-law need (~5 KB/CTA).
// warp w owns f-row w; thread (w,lane) copies w rows {j*8+w} and x row w.
// ---------------------------------------------------------------------------
__global__ __launch_bounds__(256, 2)
void big_kernel(const float* __restrict__ x,
                const float* __restrict__ W1,
                const float* __restrict__ dW1)
{
    __shared__ float4 ws[2][NROWS][KT4];   // 2 x 20 KB
    __shared__ float4 xs[2][NB][KT4];      // 2 x  4 KB   (total 48 KB)

    const int tid  = threadIdx.x;
    const int lane = tid & 31;
    const int warp = tid >> 5;
    const int f    = blockIdx.y * RF + warp;
    const long k0  = (long)blockIdx.x * KCHUNK;

    const float4* __restrict__ wrow[NW];
    wrow[0] = (const float4*)(W1 + (long)f * D_IN + k0);
    #pragma unroll
    for (int t = 0; t < NT; t++)
        wrow[t + 1] = (const float4*)(dW1 + ((long)(t * FEAT + f)) * D_IN + k0);
    const float4* __restrict__ xrow = (const float4*)(x + (long)warp * D_IN + k0);

    float acc[NW][NB];
    #pragma unroll
    for (int j = 0; j < NW; j++)
        #pragma unroll
        for (int b = 0; b < NB; b++) acc[j][b] = 0.0f;

    // prologue: prefetch tile 0 into buf 0
    {
        #pragma unroll
        for (int j = 0; j < NW; j++)
            cpa16(&ws[0][j * 8 + warp][lane], wrow[j] + lane);
        cpa16(&xs[0][warp][lane], xrow + lane);
        cpa_commit();
    }

    for (int tile = 0; tile < NTILES; tile++) {
        const int buf = tile & 1;
        if (tile + 1 < NTILES) {
            const int off = (tile + 1) * KT4 + lane;
            #pragma unroll
            for (int j = 0; j < NW; j++)
                cpa16(&ws[buf ^ 1][j * 8 + warp][lane], wrow[j] + off);
            cpa16(&xs[buf ^ 1][warp][lane], xrow + off);
            cpa_commit();
            cpa_wait<1>();
        } else {
            cpa_wait<0>();
        }
        __syncthreads();

        float4 xv[NB];
        #pragma unroll
        for (int b = 0; b < NB; b++) xv[b] = xs[buf][b][lane];
        #pragma unroll
        for (int j = 0; j < NW; j++) {
            const float4 wv = ws[buf][j * 8 + warp][lane];
            #pragma unroll
            for (int b = 0; b < NB; b++) {
                acc[j][b] = fmaf(wv.x, xv[b].x, acc[j][b]);
                acc[j][b] = fmaf(wv.y, xv[b].y, acc[j][b]);
                acc[j][b] = fmaf(wv.z, xv[b].z, acc[j][b]);
                acc[j][b] = fmaf(wv.w, xv[b].w, acc[j][b]);
            }
        }
        __syncthreads();   // protect buf before it is refilled
    }

    // warp butterfly reduction over lanes (kq slices), then lane b stores batch b
    #pragma unroll
    for (int j = 0; j < NW; j++)
        #pragma unroll
        for (int b = 0; b < NB; b++) {
            float v = acc[j][b];
            #pragma unroll
            for (int off = 16; off; off >>= 1)
                v += __shfl_xor_sync(0xffffffffu, v, off);
            if (lane == b) d_gpart[blockIdx.x][j][f][b] = v;
        }
}

// ---------------------------------------------------------------------------
// Kernel 2 (32 blocks): reduce partials -> z; emit hrelu + masked tangents.
// Also warms mW1/mW2 into L2 for fin_kernel (value-dependent dummy store).
// ---------------------------------------------------------------------------
__global__ __launch_bounds__(256)
void red_kernel(const float* __restrict__ b1, const float* __restrict__ db1,
                const float* __restrict__ mW1, const float* __restrict__ mW2)
{
    const int lane = threadIdx.x & 31;
    const int wid  = threadIdx.x >> 5;
    const int f    = blockIdx.x * 8 + wid;

    // L2 warm: pull this block's slice of mW1 (+ mW2 in block 0) into L2 now.
    float warm = __ldcg(mW1 + blockIdx.x * 512 + threadIdx.x)
               + __ldcg(mW1 + blockIdx.x * 512 + 256 + threadIdx.x);
    if (blockIdx.x == 0) warm += __ldcg(mW2 + threadIdx.x);

    float acc[NW][NB];
    #pragma unroll
    for (int j = 0; j < NW; j++)
        #pragma unroll
        for (int b = 0; b < NB; b++) acc[j][b] = 0.0f;

    // lane covers ks = lane and ks = lane + 32 (KSPLIT = 49)
    #pragma unroll
    for (int r = 0; r < 2; r++) {
        const int s = lane + 32 * r;
        if (s < KSPLIT) {
            #pragma unroll
            for (int j = 0; j < NW; j++) {
                const float4* gp = (const float4*)&d_gpart[s][j][f][0];
                float4 a = gp[0], c = gp[1];
                acc[j][0] += a.x; acc[j][1] += a.y; acc[j][2] += a.z; acc[j][3] += a.w;
                acc[j][4] += c.x; acc[j][5] += c.y; acc[j][6] += c.z; acc[j][7] += c.w;
            }
        }
    }

    // butterfly-reduce all 40 values across the warp
    #pragma unroll
    for (int off = 16; off; off >>= 1)
        #pragma unroll
        for (int j = 0; j < NW; j++)
            #pragma unroll
            for (int b = 0; b < NB; b++)
                acc[j][b] += __shfl_xor_sync(0xffffffffu, acc[j][b], off);

    // lane b (0..7) emits batch b for this f
    if (lane < NB) {
        const int b = lane;
        const float z0 = acc[0][b] + b1[f];
        d_hrelu[b][f] = fmaxf(z0, 0.0f);
        #pragma unroll
        for (int t = 0; t < NT; t++)
            d_mt[t][b][f] = (z0 > 0.0f) ? (acc[t + 1][b] + db1[t * FEAT + f]) : 0.0f;
    }

    // keep the warm loads alive (deterministic; practically never stores)
    if (warm == 1234567.891f) d_warm[blockIdx.x] = warm;
}

// ---------------------------------------------------------------------------
// Kernel 3 (256 blocks): all coef-independent matrix terms. (FROZEN)
// ---------------------------------------------------------------------------
__global__ __launch_bounds__(256)
void mat_kernel(const float* __restrict__ W2, const float* __restrict__ b2,
                const float* __restrict__ dW2, const float* __restrict__ db2)
{
    const int f2   = blockIdx.x;
    const int lane = threadIdx.x & 31;
    const int b    = threadIdx.x >> 5;

    float accB = 0.0f;
    float accW[NT] = {0.f, 0.f, 0.f, 0.f};
    float accV[NT] = {0.f, 0.f, 0.f, 0.f};

    #pragma unroll
    for (int i = 0; i < FEAT / 32; i++) {
        const int f = lane + 32 * i;
        const float hr = d_hrelu[b][f];
        const float w2 = W2[f2 * FEAT + f];
        accB = fmaf(hr, w2, accB);
        #pragma unroll
        for (int t = 0; t < NT; t++) {
            const float mt = d_mt[t][b][f];
            accW[t] = fmaf(mt, w2, accW[t]);
            const float dv = dW2[((t * FEAT + f2) * FEAT) + f];
            accV[t] = fmaf(hr, dv, accV[t]);
        }
    }

    #pragma unroll
    for (int off = 16; off; off >>= 1) {
        accB += __shfl_xor_sync(0xffffffffu, accB, off);
        #pragma unroll
        for (int t = 0; t < NT; t++) {
            accW[t] += __shfl_xor_sync(0xffffffffu, accW[t], off);
            accV[t] += __shfl_xor_sync(0xffffffffu, accV[t], off);
        }
    }

    if (lane == 0) {
        d_base[b][f2] = accB + b2[f2];
        #pragma unroll
        for (int t = 0; t < NT; t++)
            d_wv[t][b][f2] = accW[t] + accV[t] + db2[t * FEAT + f2];
    }
}

// ---------------------------------------------------------------------------
// Kernel 4 (8 blocks, one per batch): MetaNet coefs + final combine. (FROZEN)
// ---------------------------------------------------------------------------
__global__ __launch_bounds__(256)
void fin_kernel(const float* __restrict__ mW1, const float* __restrict__ mb1,
                const float* __restrict__ mW2, const float* __restrict__ mb2,
                float* __restrict__ out)
{
    __shared__ float base_s[FEAT];
    __shared__ float hid_s[NHID];
    __shared__ float coef_s[NT];

    const int b   = blockIdx.x;
    const int tid = threadIdx.x;

    base_s[tid] = d_base[b][tid];
    __syncthreads();

    // hidden[h] : h = tid>>2, quadrant q = tid&3 sums 64 ff each
    {
        const int h = tid >> 2;
        const int q = tid & 3;
        const float* wrow = mW1 + h * FEAT + q * 64;
        const float* brow = base_s + q * 64;
        float a = 0.0f;
        #pragma unroll 8
        for (int i = 0; i < 64; i++)
            a = fmaf(brow[i], wrow[i], a);
        a += __shfl_xor_sync(0xffffffffu, a, 1);
        a += __shfl_xor_sync(0xffffffffu, a, 2);
        if (q == 0) hid_s[h] = fmaxf(a + mb1[h], 0.0f);
    }
    __syncthreads();

    // coefs: 2 threads per task t (halves of the 64-dot), combined via shfl
    if (tid < 2 * NT) {
        const int t = tid >> 1;
        const int half = tid & 1;
        float c = 0.0f;
        #pragma unroll 8
        for (int h = 0; h < 32; h++)
            c = fmaf(hid_s[half * 32 + h], mW2[t * NHID + half * 32 + h], c);
        c += __shfl_xor_sync(0x000000ffu, c, 1);
        if (half == 0) coef_s[t] = c + mb2[t];
    }
    __syncthreads();

    // combine: out[b][f2] = base + sum_t coef_t * wv[t][b][f2]
    {
        float o = base_s[tid];
        #pragma unroll
        for (int t = 0; t < NT; t++)
            o = fmaf(coef_s[t], d_wv[t][b][tid], o);
        out[b * FEAT + tid] = o;
    }
}

// ---------------------------------------------------------------------------
extern "C" void kernel_launch(void* const* d_in, const int* in_sizes, int n_in,
                              void* d_out, int out_size)
{
    (void)in_sizes; (void)n_in; (void)out_size;
    const float* x   = (const float*)d_in[0];
    const float* W1  = (const float*)d_in[1];
    const float* b1  = (const float*)d_in[2];
    const float* W2  = (const float*)d_in[3];
    const float* b2  = (const float*)d_in[4];
    const float* mW1 = (const float*)d_in[5];
    const float* mb1 = (const float*)d_in[6];
    const float* mW2 = (const float*)d_in[7];
    const float* mb2 = (const float*)d_in[8];
    const float* dW1 = (const float*)d_in[9];
    const float* db1 = (const float*)d_in[10];
    const float* dW2 = (const float*)d_in[11];
    const float* db2 = (const float*)d_in[12];
    float* out = (float*)d_out;

    big_kernel<<<dim3(KSPLIT, FGROUPS), 256>>>(x, W1, dW1);
    red_kernel<<<FEAT / 8, 256>>>(b1, db1, mW1, mW2);
    mat_kernel<<<FEAT, 256>>>(W2, b2, dW2, db2);
    fin_kernel<<<NB, 256>>>(mW1, mb1, mW2, mb2, out);
}

// round 17
// speedup vs baseline: 1.8097x; 1.0205x over previous
#include <cuda_runtime.h>

#define D_IN   150528
#define FEAT   256
#define NHID   64
#define NT     4
#define NB     8

#define KSPLIT 49
#define KCHUNK 3072      /* D_IN / KSPLIT */
#define KT     128       /* floats per pipeline tile */
#define KT4    32        /* KT/4 */
#define NTILES 24        /* KCHUNK / KT */
#define RF     8
#define FGROUPS 32       /* FEAT / RF */
#define NW     5         /* W1 + 4 task dW1 */
#define NROWS  40        /* NW * RF */
#define NP     4         /* batch pairs */

typedef unsigned long long ull;

// Scratch (device globals; no runtime allocation)
__device__ float d_gpart[KSPLIT][NW][FEAT][NB];   // ~2 MB
__device__ float d_hrelu[NB][FEAT];
__device__ float d_mt[NT][NB][FEAT];              // masked tangent hidden
__device__ float d_base[NB][FEAT];
__device__ float d_wv[NT][NB][FEAT];              // (mt@W2^T + hrelu@dW2^T + db2) per task
__device__ float d_warm[FGROUPS];                 // sink for L2-warm loads

__device__ __forceinline__ void cpa16(void* smem_dst, const void* gsrc) {
    unsigned saddr = (unsigned)__cvta_generic_to_shared(smem_dst);
    asm volatile("cp.async.cg.shared.global [%0], [%1], 16;\n" :: "r"(saddr), "l"(gsrc));
}
__device__ __forceinline__ void cpa_commit() {
    asm volatile("cp.async.commit_group;\n" ::: "memory");
}
template<int N> __device__ __forceinline__ void cpa_wait() {
    asm volatile("cp.async.wait_group %0;\n" :: "n"(N) : "memory");
}

// packed f32x2 helpers (sm_103a: fma.rn.f32x2 — 2 FMAs per instruction)
__device__ __forceinline__ ull packf2(float lo, float hi) {
    ull r; asm("mov.b64 %0, {%1, %2};" : "=l"(r) : "f"(lo), "f"(hi)); return r;
}
__device__ __forceinline__ void fmaf2(ull& d, ull a, ull b) {
    asm("fma.rn.f32x2 %0, %1, %2, %3;" : "=l"(d) : "l"(a), "l"(b), "l"(d));
}
__device__ __forceinline__ float2 unpackf2(ull v) {
    float2 f; asm("mov.b64 {%0, %1}, %2;" : "=f"(f.x), "=f"(f.y) : "l"(v)); return f;
}

// ---------------------------------------------------------------------------
// Kernel 1: streaming dot products. g[j][f][b] = x[b] . Wj[f]  (no biases)
// Weights + x staged through SMEM cp.async double buffer (in-flight fix, R16
// verified). Inner loop now f32x2 packed: 80 FFMA2 + 36 packs per warp-tile
// instead of 160 FFMA — halves the fma-pipe floor so DRAM becomes the roof.
// ---------------------------------------------------------------------------
__global__ __launch_bounds__(256, 2)
void big_kernel(const float* __restrict__ x,
                const float* __restrict__ W1,
                const float* __restrict__ dW1)
{
    __shared__ float4 ws[2][NROWS][KT4];   // 2 x 20 KB
    __shared__ float4 xs[2][NB][KT4];      // 2 x  4 KB   (total 48 KB)

    const int tid  = threadIdx.x;
    const int lane = tid & 31;
    const int warp = tid >> 5;
    const int f    = blockIdx.y * RF + warp;
    const long k0  = (long)blockIdx.x * KCHUNK;

    const float4* __restrict__ wrow[NW];
    wrow[0] = (const float4*)(W1 + (long)f * D_IN + k0);
    #pragma unroll
    for (int t = 0; t < NT; t++)
        wrow[t + 1] = (const float4*)(dW1 + ((long)(t * FEAT + f)) * D_IN + k0);
    const float4* __restrict__ xrow = (const float4*)(x + (long)warp * D_IN + k0);

    ull accp[NW][NP];   // packed accumulators: pair p = (batch 2p, batch 2p+1)
    #pragma unroll
    for (int j = 0; j < NW; j++)
        #pragma unroll
        for (int p = 0; p < NP; p++) accp[j][p] = 0ull;

    // prologue: prefetch tile 0 into buf 0
    {
        #pragma unroll
        for (int j = 0; j < NW; j++)
            cpa16(&ws[0][j * 8 + warp][lane], wrow[j] + lane);
        cpa16(&xs[0][warp][lane], xrow + lane);
        cpa_commit();
    }

    for (int tile = 0; tile < NTILES; tile++) {
        const int buf = tile & 1;
        if (tile + 1 < NTILES) {
            const int off = (tile + 1) * KT4 + lane;
            #pragma unroll
            for (int j = 0; j < NW; j++)
                cpa16(&ws[buf ^ 1][j * 8 + warp][lane], wrow[j] + off);
            cpa16(&xs[buf ^ 1][warp][lane], xrow + off);
            cpa_commit();
            cpa_wait<1>();
        } else {
            cpa_wait<0>();
        }
        __syncthreads();

        // pack x batch-pairs per float4 component: 16 packs
        ull xp0[NP], xp1[NP], xp2[NP], xp3[NP];
        #pragma unroll
        for (int p = 0; p < NP; p++) {
            const float4 a = xs[buf][2 * p][lane];
            const float4 b = xs[buf][2 * p + 1][lane];
            xp0[p] = packf2(a.x, b.x);
            xp1[p] = packf2(a.y, b.y);
            xp2[p] = packf2(a.z, b.z);
            xp3[p] = packf2(a.w, b.w);
        }

        #pragma unroll
        for (int j = 0; j < NW; j++) {
            const float4 wv = ws[buf][j * 8 + warp][lane];
            const ull w0 = packf2(wv.x, wv.x);
            const ull w1 = packf2(wv.y, wv.y);
            const ull w2 = packf2(wv.z, wv.z);
            const ull w3 = packf2(wv.w, wv.w);
            #pragma unroll
            for (int p = 0; p < NP; p++) {
                fmaf2(accp[j][p], w0, xp0[p]);
                fmaf2(accp[j][p], w1, xp1[p]);
                fmaf2(accp[j][p], w2, xp2[p]);
                fmaf2(accp[j][p], w3, xp3[p]);
            }
        }
        __syncthreads();   // protect buf before it is refilled
    }

    // unpack, warp butterfly reduction, lane b stores batch b
    #pragma unroll
    for (int j = 0; j < NW; j++) {
        float acc[NB];
        #pragma unroll
        for (int p = 0; p < NP; p++) {
            const float2 v = unpackf2(accp[j][p]);
            acc[2 * p] = v.x; acc[2 * p + 1] = v.y;
        }
        #pragma unroll
        for (int b = 0; b < NB; b++) {
            float v = acc[b];
            #pragma unroll
            for (int off = 16; off; off >>= 1)
                v += __shfl_xor_sync(0xffffffffu, v, off);
            if (lane == b) d_gpart[blockIdx.x][j][f][b] = v;
        }
    }
}

// ---------------------------------------------------------------------------
// Kernel 2 (32 blocks): reduce partials -> z; emit hrelu + masked tangents.
// (L2 warm kept: neutral, avoids a new variable.)
// ---------------------------------------------------------------------------
__global__ __launch_bounds__(256)
void red_kernel(const float* __restrict__ b1, const float* __restrict__ db1,
                const float* __restrict__ mW1, const float* __restrict__ mW2)
{
    const int lane = threadIdx.x & 31;
    const int wid  = threadIdx.x >> 5;
    const int f    = blockIdx.x * 8 + wid;

    float warm = __ldcg(mW1 + blockIdx.x * 512 + threadIdx.x)
               + __ldcg(mW1 + blockIdx.x * 512 + 256 + threadIdx.x);
    if (blockIdx.x == 0) warm += __ldcg(mW2 + threadIdx.x);

    float acc[NW][NB];
    #pragma unroll
    for (int j = 0; j < NW; j++)
        #pragma unroll
        for (int b = 0; b < NB; b++) acc[j][b] = 0.0f;

    #pragma unroll
    for (int r = 0; r < 2; r++) {
        const int s = lane + 32 * r;
        if (s < KSPLIT) {
            #pragma unroll
            for (int j = 0; j < NW; j++) {
                const float4* gp = (const float4*)&d_gpart[s][j][f][0];
                float4 a = gp[0], c = gp[1];
                acc[j][0] += a.x; acc[j][1] += a.y; acc[j][2] += a.z; acc[j][3] += a.w;
                acc[j][4] += c.x; acc[j][5] += c.y; acc[j][6] += c.z; acc[j][7] += c.w;
            }
        }
    }

    #pragma unroll
    for (int off = 16; off; off >>= 1)
        #pragma unroll
        for (int j = 0; j < NW; j++)
            #pragma unroll
            for (int b = 0; b < NB; b++)
                acc[j][b] += __shfl_xor_sync(0xffffffffu, acc[j][b], off);

    if (lane < NB) {
        const int b = lane;
        const float z0 = acc[0][b] + b1[f];
        d_hrelu[b][f] = fmaxf(z0, 0.0f);
        #pragma unroll
        for (int t = 0; t < NT; t++)
            d_mt[t][b][f] = (z0 > 0.0f) ? (acc[t + 1][b] + db1[t * FEAT + f]) : 0.0f;
    }

    if (warm == 1234567.891f) d_warm[blockIdx.x] = warm;
}

// ---------------------------------------------------------------------------
// Kernel 3 (256 blocks): all coef-independent matrix terms. (FROZEN)
// ---------------------------------------------------------------------------
__global__ __launch_bounds__(256)
void mat_kernel(const float* __restrict__ W2, const float* __restrict__ b2,
                const float* __restrict__ dW2, const float* __restrict__ db2)
{
    const int f2   = blockIdx.x;
    const int lane = threadIdx.x & 31;
    const int b    = threadIdx.x >> 5;

    float accB = 0.0f;
    float accW[NT] = {0.f, 0.f, 0.f, 0.f};
    float accV[NT] = {0.f, 0.f, 0.f, 0.f};

    #pragma unroll
    for (int i = 0; i < FEAT / 32; i++) {
        const int f = lane + 32 * i;
        const float hr = d_hrelu[b][f];
        const float w2 = W2[f2 * FEAT + f];
        accB = fmaf(hr, w2, accB);
        #pragma unroll
        for (int t = 0; t < NT; t++) {
            const float mt = d_mt[t][b][f];
            accW[t] = fmaf(mt, w2, accW[t]);
            const float dv = dW2[((t * FEAT + f2) * FEAT) + f];
            accV[t] = fmaf(hr, dv, accV[t]);
        }
    }

    #pragma unroll
    for (int off = 16; off; off >>= 1) {
        accB += __shfl_xor_sync(0xffffffffu, accB, off);
        #pragma unroll
        for (int t = 0; t < NT; t++) {
            accW[t] += __shfl_xor_sync(0xffffffffu, accW[t], off);
            accV[t] += __shfl_xor_sync(0xffffffffu, accV[t], off);
        }
    }

    if (lane == 0) {
        d_base[b][f2] = accB + b2[f2];
        #pragma unroll
        for (int t = 0; t < NT; t++)
            d_wv[t][b][f2] = accW[t] + accV[t] + db2[t * FEAT + f2];
    }
}

// ---------------------------------------------------------------------------
// Kernel 4 (8 blocks, one per batch): MetaNet coefs + final combine.
// Hidden phase now float4-vectorized: 16 independent LDG.128 per thread
// (256 B in flight) instead of 64 scalar LDGs — kills the latency serialization.
// ---------------------------------------------------------------------------
__global__ __launch_bounds__(256)
void fin_kernel(const float* __restrict__ mW1, const float* __restrict__ mb1,
                const float* __restrict__ mW2, const float* __restrict__ mb2,
                float* __restrict__ out)
{
    __shared__ float base_s[FEAT];
    __shared__ float hid_s[NHID];
    __shared__ float coef_s[NT];

    const int b   = blockIdx.x;
    const int tid = threadIdx.x;

    base_s[tid] = d_base[b][tid];
    __syncthreads();

    // hidden[h]: h = tid>>2, quadrant q = tid&3 sums 64 ff each via float4
    {
        const int h = tid >> 2;
        const int q = tid & 3;
        const float4* wrow = (const float4*)(mW1 + h * FEAT + q * 64);
        const float4* brow = (const float4*)(base_s + q * 64);
        float a = 0.0f;
        #pragma unroll
        for (int i = 0; i < 16; i++) {
            const float4 w = wrow[i];
            const float4 v = brow[i];
            a = fmaf(w.x, v.x, a);
            a = fmaf(w.y, v.y, a);
            a = fmaf(w.z, v.z, a);
            a = fmaf(w.w, v.w, a);
        }
        a += __shfl_xor_sync(0xffffffffu, a, 1);
        a += __shfl_xor_sync(0xffffffffu, a, 2);
        if (q == 0) hid_s[h] = fmaxf(a + mb1[h], 0.0f);
    }
    __syncthreads();

    // coefs: 2 threads per task t (halves of the 64-dot) via float4
    if (tid < 2 * NT) {
        const int t = tid >> 1;
        const int half = tid & 1;
        const float4* wrow = (const float4*)(mW2 + t * NHID + half * 32);
        const float4* hrow = (const float4*)(hid_s + half * 32);
        float c = 0.0f;
        #pragma unroll
        for (int i = 0; i < 8; i++) {
            const float4 w = wrow[i];
            const float4 v = hrow[i];
            c = fmaf(w.x, v.x, c);
            c = fmaf(w.y, v.y, c);
            c = fmaf(w.z, v.z, c);
            c = fmaf(w.w, v.w, c);
        }
        c += __shfl_xor_sync(0x000000ffu, c, 1);
        if (half == 0) coef_s[t] = c + mb2[t];
    }
    __syncthreads();

    // combine: out[b][f2] = base + sum_t coef_t * wv[t][b][f2]
    {
        float o = base_s[tid];
        #pragma unroll
        for (int t = 0; t < NT; t++)
            o = fmaf(coef_s[t], d_wv[t][b][tid], o);
        out[b * FEAT + tid] = o;
    }
}

// ---------------------------------------------------------------------------
extern "C" void kernel_launch(void* const* d_in, const int* in_sizes, int n_in,
                              void* d_out, int out_size)
{
    (void)in_sizes; (void)n_in; (void)out_size;
    const float* x   = (const float*)d_in[0];
    const float* W1  = (const float*)d_in[1];
    const float* b1  = (const float*)d_in[2];
    const float* W2  = (const float*)d_in[3];
    const float* b2  = (const float*)d_in[4];
    const float* mW1 = (const float*)d_in[5];
    const float* mb1 = (const float*)d_in[6];
    const float* mW2 = (const float*)d_in[7];
    const float* mb2 = (const float*)d_in[8];
    const float* dW1 = (const float*)d_in[9];
    const float* db1 = (const float*)d_in[10];
    const float* dW2 = (const float*)d_in[11];
    const float* db2 = (const float*)d_in[12];
    float* out = (float*)d_out;

    big_kernel<<<dim3(KSPLIT, FGROUPS), 256>>>(x, W1, dW1);
    red_kernel<<<FEAT / 8, 256>>>(b1, db1, mW1, mW2);
    mat_kernel<<<FEAT, 256>>>(W2, b2, dW2, db2);
    fin_kernel<<<NB, 256>>>(mW1, mb1, mW2, mb2, out);
}